// round 7
// baseline (speedup 1.0000x reference)
#include <cuda_runtime.h>

// Problem constants (fixed by the dataset): N=30000, C=3, D=128, K=10, H=64
#define DD   128
#define HH   64
#define GATE 256   // 4*H per direction
#define ROW  512   // both directions of gate pre-activations

#define NMAX 30000

// Scratch (static device globals — allocation-free rule)
__device__ __align__(16) float g_gxbuf[(size_t)NMAX * 3 * ROW];   // content gate preacts (reused per s)
__device__ __align__(16) float g_gxn[(size_t)3 * NMAX * ROW];     // neighbor gate preacts per s
__device__ __align__(16) float g_content[(size_t)3 * NMAX * DD];  // content embeddings
__device__ __align__(16) float g_neigh[(size_t)9 * NMAX * DD];    // neigh[d][s][n][128]

__device__ __forceinline__ float sigm(float x) { return 1.f / (1.f + __expf(-x)); }
__device__ __forceinline__ float tanh_(float x) { return 2.f / (1.f + __expf(-2.f * x)) - 1.f; }

// ---------------------------------------------------------------------------
// GEMM: C[m][j] = sum_k A[m][k] * W[j][k] + b1[j] + b2[j]
// A: [M,128] row-major, W: [512,128] row-major, C: [M,512]
// grid: (ceil(M/64), 4)  block: 256
// ---------------------------------------------------------------------------
#define GEMM_SMEM ((128 * 68 + 128 * 132) * 4)

__global__ __launch_bounds__(256) void gemm_bias(
    const float* __restrict__ A, const float* __restrict__ W,
    const float* __restrict__ b1, const float* __restrict__ b2,
    float* __restrict__ C, int M)
{
    extern __shared__ float sm[];
    float* Ast = sm;              // [128 k][68 m]
    float* Wst = sm + 128 * 68;   // [128 k][132 j]
    const int tid = threadIdx.x;
    const int bm = blockIdx.x, jc = blockIdx.y;

    // Load A tile transposed: [64 m][128 k] -> Ast[k][m]
    for (int q = tid; q < 64 * 32; q += 256) {
        int r = q >> 5;
        int k4 = (q & 31) << 2;
        int gm = bm * 64 + r;
        float4 v = make_float4(0.f, 0.f, 0.f, 0.f);
        if (gm < M) v = *(const float4*)(A + (size_t)gm * 128 + k4);
        Ast[(k4 + 0) * 68 + r] = v.x;
        Ast[(k4 + 1) * 68 + r] = v.y;
        Ast[(k4 + 2) * 68 + r] = v.z;
        Ast[(k4 + 3) * 68 + r] = v.w;
    }
    // Load W chunk transposed: [128 j][128 k] -> Wst[k][j]
    for (int q = tid; q < 128 * 32; q += 256) {
        int jj = q >> 5;
        int k4 = (q & 31) << 2;
        float4 v = *(const float4*)(W + ((size_t)(jc * 128 + jj)) * 128 + k4);
        Wst[(k4 + 0) * 132 + jj] = v.x;
        Wst[(k4 + 1) * 132 + jj] = v.y;
        Wst[(k4 + 2) * 132 + jj] = v.z;
        Wst[(k4 + 3) * 132 + jj] = v.w;
    }
    __syncthreads();

    const int tx = tid & 15;   // j group: 8 cols
    const int ty = tid >> 4;   // m group: 4 rows
    float acc[4][8];
#pragma unroll
    for (int i = 0; i < 4; i++)
#pragma unroll
        for (int j = 0; j < 8; j++) acc[i][j] = 0.f;

#pragma unroll 4
    for (int kk = 0; kk < 128; kk++) {
        float4 a  = *(const float4*)(Ast + kk * 68 + (ty << 2));
        float4 w0 = *(const float4*)(Wst + kk * 132 + (tx << 3));
        float4 w1 = *(const float4*)(Wst + kk * 132 + (tx << 3) + 4);
        float av[4] = {a.x, a.y, a.z, a.w};
        float wv[8] = {w0.x, w0.y, w0.z, w0.w, w1.x, w1.y, w1.z, w1.w};
#pragma unroll
        for (int mi = 0; mi < 4; mi++)
#pragma unroll
            for (int ji = 0; ji < 8; ji++) acc[mi][ji] += av[mi] * wv[ji];
    }

    const int jb = (jc << 7) + (tx << 3);
    float bb[8];
#pragma unroll
    for (int ji = 0; ji < 8; ji++) bb[ji] = b1[jb + ji] + b2[jb + ji];

#pragma unroll
    for (int mi = 0; mi < 4; mi++) {
        int gm = (bm << 6) + (ty << 2) + mi;
        if (gm < M) {
            float4 o0 = make_float4(acc[mi][0] + bb[0], acc[mi][1] + bb[1],
                                    acc[mi][2] + bb[2], acc[mi][3] + bb[3]);
            float4 o1 = make_float4(acc[mi][4] + bb[4], acc[mi][5] + bb[5],
                                    acc[mi][6] + bb[6], acc[mi][7] + bb[7]);
            *(float4*)(C + (size_t)gm * ROW + jb)     = o0;
            *(float4*)(C + (size_t)gm * ROW + jb + 4) = o1;
        }
    }
}

// ---------------------------------------------------------------------------
// Bi-LSTM recurrence over precomputed gate pre-activations (bias already added).
// Per CTA: 64 nodes, one direction (blockIdx.y). Per step: register-tiled
// GEMM [64 x 256 x 64] from SMEM H-state and SMEM Whh^T, fused gate math.
// grid: (ceil(N/64), 2, pairs). idx==null -> content mode (row = n*K + t).
// idx!=null -> neighbor mode, blockIdx.z = d*3+s selects gather table & params.
// ---------------------------------------------------------------------------
#define RSMEM ((64 * 260 + 64 * 68) * 4 + 64 * 10 * 4)

__global__ __launch_bounds__(256) void bilstm_recur(
    const float* __restrict__ gx, const int* __restrict__ idx,
    const float* __restrict__ Whh, float* __restrict__ out,
    int N, int K)
{
    extern __shared__ float sm[];
    float* WhhT = sm;                    // [64 k][260 j-pitch]
    float* HsT  = sm + 64 * 260;         // [64 k][68 m-pitch]
    int*   ids  = (int*)(HsT + 64 * 68); // [64 m][K]

    const int tid = threadIdx.x;
    const int dir = blockIdx.y;

    if (idx) {
        int p = blockIdx.z;
        int d = p / 3, s = p - d * 3;
        gx  += (size_t)s * N * ROW;
        idx += (size_t)(s * 3 + d) * N * K;
        Whh += (size_t)s * 2 * GATE * HH;
        out += (size_t)(d * 3 + s) * N * DD;
    }
    Whh += (size_t)dir * GATE * HH;

    const int node0 = blockIdx.x * 64;

    // Load Whh transposed into SMEM: Whh[j][k] -> WhhT[k][j]
    for (int i = tid; i < GATE * HH; i += 256) {
        int j = i >> 6, k = i & 63;
        WhhT[k * 260 + j] = Whh[i];
    }
    // Zero H state
    for (int i = tid; i < 64 * 68; i += 256) HsT[i] = 0.f;
    // Stage gather indices
    if (idx) {
        for (int i = tid; i < 64 * K; i += 256) {
            int m = i / K;
            int n = node0 + m;
            ids[i] = (n < N) ? idx[(size_t)n * K + (i - m * K)] : 0;
        }
    }
    __syncthreads();

    const int mp = tid >> 3;        // 0..31 node pair
    const int kg = tid & 7;         // 0..7  hidden group
    const int m0 = mp * 2, m1 = m0 + 1;
    const int k0 = kg * 8;
    const int n0 = node0 + m0, n1 = node0 + m1;

    float c0[8], c1[8], hs0[8], hs1[8];
#pragma unroll
    for (int q = 0; q < 8; q++) { c0[q] = 0.f; c1[q] = 0.f; hs0[q] = 0.f; hs1[q] = 0.f; }

    for (int t = 0; t < K; t++) {
        const int tt = dir ? (K - 1 - t) : t;
        size_t row0, row1;
        if (idx) {
            row0 = (size_t)ids[m0 * K + tt];
            row1 = (size_t)ids[m1 * K + tt];
        } else {
            row0 = (size_t)(n0 < N ? n0 : 0) * K + tt;
            row1 = (size_t)(n1 < N ? n1 : 0) * K + tt;
        }
        const float* p0 = gx + row0 * ROW + dir * GATE + k0;
        const float* p1 = gx + row1 * ROW + dir * GATE + k0;

        float A0[4][8], A1[4][8];
#pragma unroll
        for (int g = 0; g < 4; g++) {
            float4 v0 = *(const float4*)(p0 + (g << 6));
            float4 v1 = *(const float4*)(p0 + (g << 6) + 4);
            A0[g][0] = v0.x; A0[g][1] = v0.y; A0[g][2] = v0.z; A0[g][3] = v0.w;
            A0[g][4] = v1.x; A0[g][5] = v1.y; A0[g][6] = v1.z; A0[g][7] = v1.w;
            float4 u0 = *(const float4*)(p1 + (g << 6));
            float4 u1 = *(const float4*)(p1 + (g << 6) + 4);
            A1[g][0] = u0.x; A1[g][1] = u0.y; A1[g][2] = u0.z; A1[g][3] = u0.w;
            A1[g][4] = u1.x; A1[g][5] = u1.y; A1[g][6] = u1.z; A1[g][7] = u1.w;
        }

        // Recurrent GEMM: A += H(prev) @ Whh^T
#pragma unroll 2
        for (int kk = 0; kk < 64; kk++) {
            float2 h2 = *(const float2*)(HsT + kk * 68 + m0);
            const float* wr = WhhT + kk * 260 + k0;
#pragma unroll
            for (int g = 0; g < 4; g++) {
                float4 w0 = *(const float4*)(wr + (g << 6));
                float4 w1 = *(const float4*)(wr + (g << 6) + 4);
                A0[g][0] += h2.x * w0.x; A0[g][1] += h2.x * w0.y;
                A0[g][2] += h2.x * w0.z; A0[g][3] += h2.x * w0.w;
                A0[g][4] += h2.x * w1.x; A0[g][5] += h2.x * w1.y;
                A0[g][6] += h2.x * w1.z; A0[g][7] += h2.x * w1.w;
                A1[g][0] += h2.y * w0.x; A1[g][1] += h2.y * w0.y;
                A1[g][2] += h2.y * w0.z; A1[g][3] += h2.y * w0.w;
                A1[g][4] += h2.y * w1.x; A1[g][5] += h2.y * w1.y;
                A1[g][6] += h2.y * w1.z; A1[g][7] += h2.y * w1.w;
            }
        }
        __syncthreads();   // all H reads done before overwrite

        // Gate math + write new H
#pragma unroll
        for (int q = 0; q < 8; q++) {
            float iv = A0[0][q], fv = A0[1][q], gv = A0[2][q], ov = A0[3][q];
            c0[q] = sigm(fv) * c0[q] + sigm(iv) * tanh_(gv);
            float h0v = sigm(ov) * tanh_(c0[q]);
            hs0[q] += h0v;

            iv = A1[0][q]; fv = A1[1][q]; gv = A1[2][q]; ov = A1[3][q];
            c1[q] = sigm(fv) * c1[q] + sigm(iv) * tanh_(gv);
            float h1v = sigm(ov) * tanh_(c1[q]);
            hs1[q] += h1v;

            *(float2*)(HsT + (k0 + q) * 68 + m0) = make_float2(h0v, h1v);
        }
        __syncthreads();   // new H visible before next step
    }

    const float inv = 1.f / (float)K;
    if (n0 < N) {
        float4 o0 = make_float4(hs0[0] * inv, hs0[1] * inv, hs0[2] * inv, hs0[3] * inv);
        float4 o1 = make_float4(hs0[4] * inv, hs0[5] * inv, hs0[6] * inv, hs0[7] * inv);
        *(float4*)(out + (size_t)n0 * DD + dir * HH + k0)     = o0;
        *(float4*)(out + (size_t)n0 * DD + dir * HH + k0 + 4) = o1;
    }
    if (n1 < N) {
        float4 o0 = make_float4(hs1[0] * inv, hs1[1] * inv, hs1[2] * inv, hs1[3] * inv);
        float4 o1 = make_float4(hs1[4] * inv, hs1[5] * inv, hs1[6] * inv, hs1[7] * inv);
        *(float4*)(out + (size_t)n1 * DD + dir * HH + k0)     = o0;
        *(float4*)(out + (size_t)n1 * DD + dir * HH + k0 + 4) = o1;
    }
}

// ---------------------------------------------------------------------------
// Attention fusion: one warp per (d, n).
// slots = [neigh[d][0], neigh[d][1], neigh[d][2], content[d]]
// logit_s = leaky_relu(dot(d_h, w[:128]) + dot(slot_s, w[128:]) + b)
// out = softmax(logits) . slots
// ---------------------------------------------------------------------------
__global__ void attn_fuse(const float* __restrict__ content,
                          const float* __restrict__ neigh,
                          const float* __restrict__ attn_w,
                          const float* __restrict__ attn_b,
                          float* __restrict__ out, int N)
{
    int w = (blockIdx.x * blockDim.x + threadIdx.x) >> 5;
    if (w >= 3 * N) return;
    int lane = threadIdx.x & 31;
    int d = w / N, n = w - d * N;

    const float* dh = content + ((size_t)d * N + n) * DD;
    const float* aw = attn_w + d * 256;
    float4 w1 = *(const float4*)(aw + lane * 4);
    float4 w2 = *(const float4*)(aw + 128 + lane * 4);

    float4 s[4];
#pragma unroll
    for (int i = 0; i < 3; i++)
        s[i] = *(const float4*)(neigh + (((size_t)(d * 3 + i)) * N + n) * DD + lane * 4);
    s[3] = *(const float4*)(dh + lane * 4);

    float base = s[3].x * w1.x + s[3].y * w1.y + s[3].z * w1.z + s[3].w * w1.w;
    float l[4];
#pragma unroll
    for (int i = 0; i < 4; i++)
        l[i] = s[i].x * w2.x + s[i].y * w2.y + s[i].z * w2.z + s[i].w * w2.w;

#pragma unroll
    for (int off = 16; off; off >>= 1) {
        base += __shfl_xor_sync(0xffffffffu, base, off);
#pragma unroll
        for (int i = 0; i < 4; i++) l[i] += __shfl_xor_sync(0xffffffffu, l[i], off);
    }

    float b = attn_b[d];
    float mx = -1e30f;
#pragma unroll
    for (int i = 0; i < 4; i++) {
        float v = base + l[i] + b;
        l[i] = v > 0.f ? v : 0.01f * v;
        mx = fmaxf(mx, l[i]);
    }
    float se = 0.f;
#pragma unroll
    for (int i = 0; i < 4; i++) { l[i] = __expf(l[i] - mx); se += l[i]; }
    float inv = 1.f / se;

    float4 o = make_float4(0.f, 0.f, 0.f, 0.f);
#pragma unroll
    for (int i = 0; i < 4; i++) {
        float wi = l[i] * inv;
        o.x += wi * s[i].x; o.y += wi * s[i].y; o.z += wi * s[i].z; o.w += wi * s[i].w;
    }
    *(float4*)(out + ((size_t)d * N + n) * DD + lane * 4) = o;
}

// ---------------------------------------------------------------------------
extern "C" void kernel_launch(void* const* d_in, const int* in_sizes, int n_in,
                              void* d_out, int out_size)
{
    const float* xs[3]   = {(const float*)d_in[0], (const float*)d_in[1], (const float*)d_in[2]};
    const float* Wih_c   = (const float*)d_in[3];
    const float* Whh_c   = (const float*)d_in[4];
    const float* bih_c   = (const float*)d_in[5];
    const float* bhh_c   = (const float*)d_in[6];
    const float* Wih_n   = (const float*)d_in[7];
    const float* Whh_n   = (const float*)d_in[8];
    const float* bih_n   = (const float*)d_in[9];
    const float* bhh_n   = (const float*)d_in[10];
    const float* attn_w  = (const float*)d_in[11];
    const float* attn_b  = (const float*)d_in[12];
    const int*   nbr     = (const int*)d_in[13];
    float* out = (float*)d_out;

    const int N = in_sizes[0] / (3 * DD);   // 30000

    float *gxbuf, *gxn, *content, *neigh;
    cudaGetSymbolAddress((void**)&gxbuf,   g_gxbuf);
    cudaGetSymbolAddress((void**)&gxn,     g_gxn);
    cudaGetSymbolAddress((void**)&content, g_content);
    cudaGetSymbolAddress((void**)&neigh,   g_neigh);

    cudaFuncSetAttribute(gemm_bias,    cudaFuncAttributeMaxDynamicSharedMemorySize, GEMM_SMEM);
    cudaFuncSetAttribute(bilstm_recur, cudaFuncAttributeMaxDynamicSharedMemorySize, RSMEM);

    const int nt = (N + 63) / 64;

    // Stage A+B: content bi-LSTM per feature set (shared weights)
    for (int s = 0; s < 3; s++) {
        gemm_bias<<<dim3((3 * N + 63) / 64, 4), 256, GEMM_SMEM>>>(
            xs[s], Wih_c, bih_c, bhh_c, gxbuf, 3 * N);
        bilstm_recur<<<dim3(nt, 2, 1), 256, RSMEM>>>(
            gxbuf, nullptr, Whh_c, content + (size_t)s * N * DD, N, 3);
    }

    // Stage C: precompute neighbor gate pre-activations per source type
    for (int s = 0; s < 3; s++) {
        gemm_bias<<<dim3(nt, 4), 256, GEMM_SMEM>>>(
            content + (size_t)s * N * DD,
            Wih_n + (size_t)s * ROW * DD,
            bih_n + s * ROW, bhh_n + s * ROW,
            gxn + (size_t)s * N * ROW, N);
    }

    // Stage D: 9 neighbor bi-LSTM reductions (gather pre-activations)
    bilstm_recur<<<dim3(nt, 2, 9), 256, RSMEM>>>(gxn, nbr, Whh_n, neigh, N, 10);

    // Stage E: attention fusion
    attn_fuse<<<(3 * N + 7) / 8, 256>>>(content, neigh, attn_w, attn_b, out, N);
}

// round 8
// speedup vs baseline: 1.9310x; 1.9310x over previous
#include <cuda_runtime.h>

// Problem constants (fixed by the dataset): N=30000, C=3, D=128, K=10, H=64
#define DD   128
#define HH   64
#define GATE 256   // 4*H per direction
#define ROW  512   // both directions of gate pre-activations

#define NMAX 30000

// Scratch (static device globals — allocation-free rule)
__device__ __align__(16) float g_gxbuf[(size_t)NMAX * 3 * ROW];   // content gate preacts (reused per s)
__device__ __align__(16) float g_gxn[(size_t)3 * NMAX * ROW];     // neighbor gate preacts per s
__device__ __align__(16) float g_content[(size_t)3 * NMAX * DD];  // content embeddings
__device__ __align__(16) float g_neigh[(size_t)9 * NMAX * DD];    // neigh[d][s][n][128]

__device__ __forceinline__ float sigm(float x) { return 1.f / (1.f + __expf(-x)); }
__device__ __forceinline__ float tanh_(float x) { return 2.f / (1.f + __expf(-2.f * x)) - 1.f; }

// ---------------------------------------------------------------------------
// GEMM: C[m][j] = sum_k A[m][k] * W[j][k] + b1[j] + b2[j]
// A: [M,128] row-major, W: [512,128] row-major, C: [M,512]
// grid: (ceil(M/64), 4)  block: 256
// ---------------------------------------------------------------------------
#define GEMM_SMEM ((128 * 68 + 128 * 132) * 4)

__global__ __launch_bounds__(256) void gemm_bias(
    const float* __restrict__ A, const float* __restrict__ W,
    const float* __restrict__ b1, const float* __restrict__ b2,
    float* __restrict__ C, int M)
{
    extern __shared__ float sm[];
    float* Ast = sm;              // [128 k][68 m]
    float* Wst = sm + 128 * 68;   // [128 k][132 j]
    const int tid = threadIdx.x;
    const int bm = blockIdx.x, jc = blockIdx.y;

    for (int q = tid; q < 64 * 32; q += 256) {
        int r = q >> 5;
        int k4 = (q & 31) << 2;
        int gm = bm * 64 + r;
        float4 v = make_float4(0.f, 0.f, 0.f, 0.f);
        if (gm < M) v = *(const float4*)(A + (size_t)gm * 128 + k4);
        Ast[(k4 + 0) * 68 + r] = v.x;
        Ast[(k4 + 1) * 68 + r] = v.y;
        Ast[(k4 + 2) * 68 + r] = v.z;
        Ast[(k4 + 3) * 68 + r] = v.w;
    }
    for (int q = tid; q < 128 * 32; q += 256) {
        int jj = q >> 5;
        int k4 = (q & 31) << 2;
        float4 v = *(const float4*)(W + ((size_t)(jc * 128 + jj)) * 128 + k4);
        Wst[(k4 + 0) * 132 + jj] = v.x;
        Wst[(k4 + 1) * 132 + jj] = v.y;
        Wst[(k4 + 2) * 132 + jj] = v.z;
        Wst[(k4 + 3) * 132 + jj] = v.w;
    }
    __syncthreads();

    const int tx = tid & 15;   // j group: 8 cols
    const int ty = tid >> 4;   // m group: 4 rows
    float acc[4][8];
#pragma unroll
    for (int i = 0; i < 4; i++)
#pragma unroll
        for (int j = 0; j < 8; j++) acc[i][j] = 0.f;

#pragma unroll 4
    for (int kk = 0; kk < 128; kk++) {
        float4 a  = *(const float4*)(Ast + kk * 68 + (ty << 2));
        float4 w0 = *(const float4*)(Wst + kk * 132 + (tx << 3));
        float4 w1 = *(const float4*)(Wst + kk * 132 + (tx << 3) + 4);
        float av[4] = {a.x, a.y, a.z, a.w};
        float wv[8] = {w0.x, w0.y, w0.z, w0.w, w1.x, w1.y, w1.z, w1.w};
#pragma unroll
        for (int mi = 0; mi < 4; mi++)
#pragma unroll
            for (int ji = 0; ji < 8; ji++) acc[mi][ji] += av[mi] * wv[ji];
    }

    const int jb = (jc << 7) + (tx << 3);
    float bb[8];
#pragma unroll
    for (int ji = 0; ji < 8; ji++) bb[ji] = b1[jb + ji] + b2[jb + ji];

#pragma unroll
    for (int mi = 0; mi < 4; mi++) {
        int gm = (bm << 6) + (ty << 2) + mi;
        if (gm < M) {
            float4 o0 = make_float4(acc[mi][0] + bb[0], acc[mi][1] + bb[1],
                                    acc[mi][2] + bb[2], acc[mi][3] + bb[3]);
            float4 o1 = make_float4(acc[mi][4] + bb[4], acc[mi][5] + bb[5],
                                    acc[mi][6] + bb[6], acc[mi][7] + bb[7]);
            *(float4*)(C + (size_t)gm * ROW + jb)     = o0;
            *(float4*)(C + (size_t)gm * ROW + jb + 4) = o1;
        }
    }
}

// ---------------------------------------------------------------------------
// Bi-LSTM recurrence, v2: square 8x8 thread tile.
// CTA: 64 nodes x 256 gate-cols, 256 threads.
//   ng = tid>>5  -> nodes mbase..mbase+7 (mbase = ng*8); whole warp shares ng
//                   so the H-state read per kk is a warp broadcast.
//   kg = tid&31  -> hidden units u0 = 2kg, 2kg+1; cols {g*64+u0, g*64+u0+1}.
// Per kk per lane: 8B W (x4 gates = 32B) + 32B H (broadcast) for 64 FMAs.
// H state double-buffered in SMEM -> one barrier per timestep.
// grid: (ceil(N/64), 2, pairs). idx==null -> content mode (row = n*K + t).
// idx!=null -> neighbor mode, blockIdx.z = d*3+s selects gather table/params.
// ---------------------------------------------------------------------------
#define HPITCH 68
#define RSMEM ((64 * 260 + 2 * 64 * HPITCH) * 4 + 64 * 10 * 4)

__global__ __launch_bounds__(256, 2) void bilstm_recur(
    const float* __restrict__ gx, const int* __restrict__ idx,
    const float* __restrict__ Whh, float* __restrict__ out,
    int N, int K)
{
    extern __shared__ float sm[];
    float* WhhT = sm;                          // [64 k][260 j-pitch]
    float* Hs0  = sm + 64 * 260;               // [64 u][68 m-pitch]
    float* Hs1  = Hs0 + 64 * HPITCH;
    int*   ids  = (int*)(Hs1 + 64 * HPITCH);   // [64 m][K]

    const int tid = threadIdx.x;
    const int dir = blockIdx.y;

    if (idx) {
        int p = blockIdx.z;
        int d = p / 3, s = p - d * 3;
        gx  += (size_t)s * N * ROW;
        idx += (size_t)(s * 3 + d) * N * K;
        Whh += (size_t)s * 2 * GATE * HH;
        out += (size_t)(d * 3 + s) * N * DD;
    }
    Whh += (size_t)dir * GATE * HH;
    const int node0 = blockIdx.x * 64;

    // Whh[j][k] -> WhhT[k][j]
    for (int i = tid; i < GATE * HH; i += 256) {
        int j = i >> 6, k = i & 63;
        WhhT[k * 260 + j] = Whh[i];
    }
    for (int i = tid; i < 64 * HPITCH; i += 256) Hs0[i] = 0.f;
    if (idx) {
        for (int i = tid; i < 64 * K; i += 256) {
            int m = i / K;
            int n = node0 + m;
            ids[i] = (n < N) ? idx[(size_t)n * K + (i - m * K)] : 0;
        }
    }
    __syncthreads();

    const int ng = tid >> 5;
    const int kg = tid & 31;
    const int u0 = kg << 1;
    const int mbase = ng << 3;

    float c[2][8], hsum[2][8];
#pragma unroll
    for (int u = 0; u < 2; u++)
#pragma unroll
        for (int i = 0; i < 8; i++) { c[u][i] = 0.f; hsum[u][i] = 0.f; }

    const float* gbase = gx + dir * GATE + u0;

    for (int t = 0; t < K; t++) {
        const int tt = dir ? (K - 1 - t) : t;

        // Load gate pre-activations straight into accumulators.
        float A[4][2][8];
#pragma unroll
        for (int i = 0; i < 8; i++) {
            int m = mbase + i;
            size_t row;
            if (idx) {
                row = (size_t)ids[m * K + tt];
            } else {
                int n = node0 + m;
                row = (size_t)(n < N ? n : 0) * K + tt;
            }
            const float* pr = gbase + row * ROW;
#pragma unroll
            for (int g = 0; g < 4; g++) {
                float2 v = *(const float2*)(pr + (g << 6));
                A[g][0][i] = v.x;
                A[g][1][i] = v.y;
            }
        }

        const float* Hr = (t & 1) ? Hs1 : Hs0;
        float*       Hw = (t & 1) ? Hs0 : Hs1;

        // A += H(prev) @ Whh^T   (64 x 8cols x 64k per thread-tile slice)
#pragma unroll 2
        for (int kk = 0; kk < 64; kk++) {
            float4 h0 = *(const float4*)(Hr + kk * HPITCH + mbase);
            float4 h1 = *(const float4*)(Hr + kk * HPITCH + mbase + 4);
            const float* wr = WhhT + kk * 260 + u0;
#pragma unroll
            for (int g = 0; g < 4; g++) {
                float2 w = *(const float2*)(wr + (g << 6));
                A[g][0][0] += h0.x * w.x; A[g][0][1] += h0.y * w.x;
                A[g][0][2] += h0.z * w.x; A[g][0][3] += h0.w * w.x;
                A[g][0][4] += h1.x * w.x; A[g][0][5] += h1.y * w.x;
                A[g][0][6] += h1.z * w.x; A[g][0][7] += h1.w * w.x;
                A[g][1][0] += h0.x * w.y; A[g][1][1] += h0.y * w.y;
                A[g][1][2] += h0.z * w.y; A[g][1][3] += h0.w * w.y;
                A[g][1][4] += h1.x * w.y; A[g][1][5] += h1.y * w.y;
                A[g][1][6] += h1.z * w.y; A[g][1][7] += h1.w * w.y;
            }
        }

        // Gate math + write new H into the other buffer.
#pragma unroll
        for (int u = 0; u < 2; u++) {
            float hv[8];
#pragma unroll
            for (int i = 0; i < 8; i++) {
                float iv = A[0][u][i], fv = A[1][u][i];
                float gv = A[2][u][i], ov = A[3][u][i];
                c[u][i] = sigm(fv) * c[u][i] + sigm(iv) * tanh_(gv);
                hv[i] = sigm(ov) * tanh_(c[u][i]);
                hsum[u][i] += hv[i];
            }
            *(float4*)(Hw + (u0 + u) * HPITCH + mbase) =
                make_float4(hv[0], hv[1], hv[2], hv[3]);
            *(float4*)(Hw + (u0 + u) * HPITCH + mbase + 4) =
                make_float4(hv[4], hv[5], hv[6], hv[7]);
        }
        __syncthreads();   // step t fully done before step t+1 overwrites Hr
    }

    const float inv = 1.f / (float)K;
#pragma unroll
    for (int i = 0; i < 8; i++) {
        int n = node0 + mbase + i;
        if (n < N) {
            *(float2*)(out + (size_t)n * DD + dir * HH + u0) =
                make_float2(hsum[0][i] * inv, hsum[1][i] * inv);
        }
    }
}

// ---------------------------------------------------------------------------
// Attention fusion: one warp per (d, n).
// ---------------------------------------------------------------------------
__global__ void attn_fuse(const float* __restrict__ content,
                          const float* __restrict__ neigh,
                          const float* __restrict__ attn_w,
                          const float* __restrict__ attn_b,
                          float* __restrict__ out, int N)
{
    int w = (blockIdx.x * blockDim.x + threadIdx.x) >> 5;
    if (w >= 3 * N) return;
    int lane = threadIdx.x & 31;
    int d = w / N, n = w - d * N;

    const float* dh = content + ((size_t)d * N + n) * DD;
    const float* aw = attn_w + d * 256;
    float4 w1 = *(const float4*)(aw + lane * 4);
    float4 w2 = *(const float4*)(aw + 128 + lane * 4);

    float4 s[4];
#pragma unroll
    for (int i = 0; i < 3; i++)
        s[i] = *(const float4*)(neigh + (((size_t)(d * 3 + i)) * N + n) * DD + lane * 4);
    s[3] = *(const float4*)(dh + lane * 4);

    float base = s[3].x * w1.x + s[3].y * w1.y + s[3].z * w1.z + s[3].w * w1.w;
    float l[4];
#pragma unroll
    for (int i = 0; i < 4; i++)
        l[i] = s[i].x * w2.x + s[i].y * w2.y + s[i].z * w2.z + s[i].w * w2.w;

#pragma unroll
    for (int off = 16; off; off >>= 1) {
        base += __shfl_xor_sync(0xffffffffu, base, off);
#pragma unroll
        for (int i = 0; i < 4; i++) l[i] += __shfl_xor_sync(0xffffffffu, l[i], off);
    }

    float b = attn_b[d];
    float mx = -1e30f;
#pragma unroll
    for (int i = 0; i < 4; i++) {
        float v = base + l[i] + b;
        l[i] = v > 0.f ? v : 0.01f * v;
        mx = fmaxf(mx, l[i]);
    }
    float se = 0.f;
#pragma unroll
    for (int i = 0; i < 4; i++) { l[i] = __expf(l[i] - mx); se += l[i]; }
    float inv = 1.f / se;

    float4 o = make_float4(0.f, 0.f, 0.f, 0.f);
#pragma unroll
    for (int i = 0; i < 4; i++) {
        float wi = l[i] * inv;
        o.x += wi * s[i].x; o.y += wi * s[i].y; o.z += wi * s[i].z; o.w += wi * s[i].w;
    }
    *(float4*)(out + ((size_t)d * N + n) * DD + lane * 4) = o;
}

// ---------------------------------------------------------------------------
extern "C" void kernel_launch(void* const* d_in, const int* in_sizes, int n_in,
                              void* d_out, int out_size)
{
    const float* xs[3]   = {(const float*)d_in[0], (const float*)d_in[1], (const float*)d_in[2]};
    const float* Wih_c   = (const float*)d_in[3];
    const float* Whh_c   = (const float*)d_in[4];
    const float* bih_c   = (const float*)d_in[5];
    const float* bhh_c   = (const float*)d_in[6];
    const float* Wih_n   = (const float*)d_in[7];
    const float* Whh_n   = (const float*)d_in[8];
    const float* bih_n   = (const float*)d_in[9];
    const float* bhh_n   = (const float*)d_in[10];
    const float* attn_w  = (const float*)d_in[11];
    const float* attn_b  = (const float*)d_in[12];
    const int*   nbr     = (const int*)d_in[13];
    float* out = (float*)d_out;

    const int N = in_sizes[0] / (3 * DD);   // 30000

    float *gxbuf, *gxn, *content, *neigh;
    cudaGetSymbolAddress((void**)&gxbuf,   g_gxbuf);
    cudaGetSymbolAddress((void**)&gxn,     g_gxn);
    cudaGetSymbolAddress((void**)&content, g_content);
    cudaGetSymbolAddress((void**)&neigh,   g_neigh);

    cudaFuncSetAttribute(gemm_bias,    cudaFuncAttributeMaxDynamicSharedMemorySize, GEMM_SMEM);
    cudaFuncSetAttribute(bilstm_recur, cudaFuncAttributeMaxDynamicSharedMemorySize, RSMEM);

    const int nt = (N + 63) / 64;

    // Stage A+B: content bi-LSTM per feature set (shared weights)
    for (int s = 0; s < 3; s++) {
        gemm_bias<<<dim3((3 * N + 63) / 64, 4), 256, GEMM_SMEM>>>(
            xs[s], Wih_c, bih_c, bhh_c, gxbuf, 3 * N);
        bilstm_recur<<<dim3(nt, 2, 1), 256, RSMEM>>>(
            gxbuf, nullptr, Whh_c, content + (size_t)s * N * DD, N, 3);
    }

    // Stage C: precompute neighbor gate pre-activations per source type
    for (int s = 0; s < 3; s++) {
        gemm_bias<<<dim3(nt, 4), 256, GEMM_SMEM>>>(
            content + (size_t)s * N * DD,
            Wih_n + (size_t)s * ROW * DD,
            bih_n + s * ROW, bhh_n + s * ROW,
            gxn + (size_t)s * N * ROW, N);
    }

    // Stage D: 9 neighbor bi-LSTM reductions (gather pre-activations)
    bilstm_recur<<<dim3(nt, 2, 9), 256, RSMEM>>>(gxn, nbr, Whh_n, neigh, N, 10);

    // Stage E: attention fusion
    attn_fuse<<<(3 * N + 7) / 8, 256>>>(content, neigh, attn_w, attn_b, out, N);
}